// round 17
// baseline (speedup 1.0000x reference)
#include <cuda_runtime.h>
#include <cstdint>

#define Bz 128
#define Sz 512
#define Hz 256
#define Vz 256
#define NP1 128          // phase-1 CTAs: 8 b-tile-pairs x 16 j-tiles(16 wide)
#define NWORK 20         // dedicated worker CTAs
#define NTILE 1024       // 512 t x 2 b-halves
#define HSP 264          // hs row pad (floats)

typedef unsigned long long ull;

// h sequence, slab 0 = h0 = zeros (never written). Layout [t][b][j].
__device__ float g_hseq[Sz + 1][Bz][Hz];   // ~67 MB, zero-init at module load
// one counter per b-tile (chain), own 128-B L2 line.
// value = 16 * (#steps published) -- 16 j-CTAs arrive per chain per step.
__device__ unsigned g_bar[16 * 32];
__device__ unsigned g_next = 0;            // phase-2 tile work queue
__device__ unsigned g_done = 0;            // end-of-kernel reset rendezvous (148)

__device__ __forceinline__ void fma2(ull& acc, ull a, ull b) {
    asm("fma.rn.f32x2 %0, %1, %2, %3;" : "=l"(acc) : "l"(a), "l"(b), "l"(acc));
}
__device__ __forceinline__ float f2sum(ull v) {
    return __uint_as_float((unsigned)v) + __uint_as_float((unsigned)(v >> 32));
}
__device__ __forceinline__ float sigmf(float v) { return 1.0f / (1.0f + __expf(-v)); }

__device__ __forceinline__ void red_release_gpu(unsigned* p) {
    asm volatile("red.release.gpu.add.u32 [%0], 1;" :: "l"(p) : "memory");
}
__device__ __forceinline__ unsigned ld_acquire_gpu(unsigned* p) {
    unsigned v;
    asm volatile("ld.acquire.gpu.u32 %0, [%1];" : "=r"(v) : "l"(p) : "memory");
    return v;
}

// ---- phase-1 smem layout (offsets in floats), 2-chain kernel ----
#define OFF_WRZ 0        // float4[128 kp][16 j]   8192
#define OFF_WN  8192     // float2[128 kp][16 j]   4096
#define OFF_HA  12288    // float [8 b][HSP]       2112
#define OFF_HB  14400    // float [8 b][HSP]       2112
#define OFF_RED 16512    // float4[8 kc][8 b][16 j] 4096
#define OFF_WIH 20608    // float4[16 e][16 j]     1024
#define OFF_EMB 21632    // float [256 v][17]      4352
#define OFF_X   25984    // int   [16 b][512 s]    8192
#define SM1_FLOATS 34176

// ---- phase-2 tile smem layout ----
#define HP 258
#define WP 258
#define SM2_FLOATS (64 * HP + 128 * WP)   // 49536 floats = 198144 B
#define SMEM_BYTES (SM2_FLOATS * 4)

__device__ __forceinline__ float3 compute_gi2(const float* sm, int xrow, int fj,
                                              int t, float3 bih) {
    const int* xs = (const int*)(sm + OFF_X);
    int xv = xs[xrow * Sz + t];
    float3 acc = bih;
    const float* emb = sm + OFF_EMB;
    const float4* wih = (const float4*)(sm + OFF_WIH);
#pragma unroll
    for (int e = 0; e < 16; ++e) {
        float ev = emb[xv * 17 + e];
        float4 wv = wih[e * 16 + fj];
        acc.x += ev * wv.x; acc.y += ev * wv.y; acc.z += ev * wv.z;
    }
    return acc;
}

// ---------------------------------------------------------------------------
// Phase-2 tile body (proven): out[b0..b0+64, t, :] = h_{t+1} @ W_out + b_out.
// ---------------------------------------------------------------------------
__device__ void p2_tile(float* sm2, int tid, int t, int b0,
                        const float* __restrict__ W_out,
                        const float* __restrict__ b_out,
                        float* __restrict__ out)
{
    float* hs  = sm2;              // [64 b][HP]
    float* wsT = sm2 + 64 * HP;    // [128 v][WP]

    for (int i = tid; i < 64 * 128; i += 256) {
        int bb = i >> 7, c2 = i & 127;
        *(float2*)&hs[bb * HP + c2 * 2] =
            *(const float2*)&g_hseq[t + 1][b0 + bb][c2 * 2];
    }
    const int bi = tid & 15;
    const int vi = tid >> 4;

    for (int ch = 0; ch < 2; ++ch) {
        if (ch) __syncthreads();
        for (int r = 0; r < 32; ++r) {
            int i = tid + 256 * r;
            int k = i >> 5, c4 = i & 31;
            float4 wv = *(const float4*)&W_out[k * 256 + ch * 128 + c4 * 4];
            wsT[(4 * c4 + 0) * WP + k] = wv.x;
            wsT[(4 * c4 + 1) * WP + k] = wv.y;
            wsT[(4 * c4 + 2) * WP + k] = wv.z;
            wsT[(4 * c4 + 3) * WP + k] = wv.w;
        }
        __syncthreads();

        ull acc[4][8];
#pragma unroll
        for (int ib = 0; ib < 4; ++ib)
#pragma unroll
            for (int iv = 0; iv < 8; ++iv) acc[ib][iv] = 0ull;

        const float* hB = &hs[(4 * bi) * HP];
        const float* wB = &wsT[(8 * vi) * WP];

#pragma unroll 4
        for (int kp = 0; kp < 128; ++kp) {
            ull h0 = *(const ull*)&hB[0 * HP + 2 * kp];
            ull h1 = *(const ull*)&hB[1 * HP + 2 * kp];
            ull h2 = *(const ull*)&hB[2 * HP + 2 * kp];
            ull h3 = *(const ull*)&hB[3 * HP + 2 * kp];
            ull wv[8];
#pragma unroll
            for (int iv = 0; iv < 8; ++iv)
                wv[iv] = *(const ull*)&wB[iv * WP + 2 * kp];
#pragma unroll
            for (int iv = 0; iv < 8; ++iv) {
                fma2(acc[0][iv], h0, wv[iv]);
                fma2(acc[1][iv], h1, wv[iv]);
                fma2(acc[2][iv], h2, wv[iv]);
                fma2(acc[3][iv], h3, wv[iv]);
            }
        }

        int vb = ch * 128 + 8 * vi;
        float4 boA = *(const float4*)&b_out[vb];
        float4 boB = *(const float4*)&b_out[vb + 4];
#pragma unroll
        for (int ib = 0; ib < 4; ++ib) {
            float4 oA, oB;
            oA.x = f2sum(acc[ib][0]) + boA.x;
            oA.y = f2sum(acc[ib][1]) + boA.y;
            oA.z = f2sum(acc[ib][2]) + boA.z;
            oA.w = f2sum(acc[ib][3]) + boA.w;
            oB.x = f2sum(acc[ib][4]) + boB.x;
            oB.y = f2sum(acc[ib][5]) + boB.y;
            oB.z = f2sum(acc[ib][6]) + boB.z;
            oB.w = f2sum(acc[ib][7]) + boB.w;
            size_t obase = (size_t)(b0 + 4 * bi + ib) * (Sz * Vz)
                         + (size_t)t * Vz + vb;
            *(float4*)&out[obase]     = oA;
            *(float4*)&out[obase + 4] = oB;
        }
    }
}

__device__ void p2_queue_loop(float* sm2, int tid,
                              const float* __restrict__ W_out,
                              const float* __restrict__ b_out,
                              float* __restrict__ out,
                              unsigned* s_tau)
{
    for (;;) {
        if (tid == 0) *s_tau = atomicAdd(&g_next, 1u);
        __syncthreads();
        unsigned tau = *s_tau;
        if (tau >= NTILE) break;
        const int t = (int)(tau >> 1), bh = (int)(tau & 1);
        if (tid < 8) {
            unsigned* f = &g_bar[(bh * 8 + tid) * 32];
            unsigned tgt = 16u * (unsigned)(t + 1);   // 16 arrivals per step
            while (ld_acquire_gpu(f) < tgt) { }
        }
        __syncthreads();
        p2_tile(sm2, tid, t, bh * 64, W_out, b_out, out);
    }
}

// per-chain kloop over own k-quarter; hs is the chain's staged tile
__device__ __forceinline__ void chain_kloop(const float* hs, const float4* wrz4,
                                            const float2* wn2_, int w, int bh,
                                            int j2l, float4* red4)
{
    ull ar[4], az[4], an[4];
#pragma unroll
    for (int b = 0; b < 4; ++b) { ar[b] = 0ull; az[b] = 0ull; an[b] = 0ull; }
    const int kp0 = w * 16;
#pragma unroll
    for (int q = 0; q < 8; ++q) {
        const int kb = w * 32 + q * 4;
        ulonglong2 h01[4];
#pragma unroll
        for (int b = 0; b < 4; ++b)
            h01[b] = *(const ulonglong2*)&hs[(4 * bh + b) * HSP + kb];
#pragma unroll
        for (int p = 0; p < 2; ++p) {
            const int kp = kp0 + q * 2 + p;
            ulonglong2 wrz = *(const ulonglong2*)&wrz4[kp * 16 + j2l];
            ull        wn  = *(const ull*)&wn2_[kp * 16 + j2l];
#pragma unroll
            for (int b = 0; b < 4; ++b) {
                ull h = p ? h01[b].y : h01[b].x;
                fma2(ar[b], h, wrz.x);
                fma2(az[b], h, wrz.y);
                fma2(an[b], h, wn);
            }
        }
    }
#pragma unroll
    for (int b = 0; b < 4; ++b)
        red4[(w * 8 + 4 * bh + b) * 16 + j2l] =
            make_float4(f2sum(ar[b]), f2sum(az[b]), f2sum(an[b]), 0.f);
}

// ---------------------------------------------------------------------------
// Fused kernel, grid = 148 (all co-resident):
//   bid < 128 : TWO-CHAIN recurrence. CTA (btp, jt) owns chains btA=2btp,
//               btB=2btp+1 on j-slice [16jt,16jt+16). Phases alternate; each
//               chain's exchange latency hides under the other's kloop.
//   bid >= 128: phase-2 worker (gated tile queue). Phase-1 CTAs join after.
// ---------------------------------------------------------------------------
__global__ void __launch_bounds__(256, 1)
gru_fused(const int* __restrict__ x,
          const float* __restrict__ embed,
          const float* __restrict__ W_ih, const float* __restrict__ b_ih,
          const float* __restrict__ W_hh, const float* __restrict__ b_hh,
          const float* __restrict__ W_out, const float* __restrict__ b_out,
          float* __restrict__ out)
{
    extern __shared__ float sm[];
    __shared__ unsigned s_tau;
    const int tid = threadIdx.x;

    if (blockIdx.x < NP1) {
        const int jt = blockIdx.x & 15, btp = blockIdx.x >> 4;
        const int j0 = jt * 16;
        const int bA0 = btp * 16, bB0 = btp * 16 + 8;
        const int btA = 2 * btp, btB = 2 * btp + 1;

        // ---- one-time fills ----
        float4* wrz4 = (float4*)(sm + OFF_WRZ);
        float2* wn2_ = (float2*)(sm + OFF_WN);
        for (int i = tid; i < 128 * 16; i += 256) {
            int kp = i >> 4, j2 = i & 15, jg = j0 + j2;
            const float* wr0 = W_hh + (2 * kp) * 768 + jg;
            const float* wr1 = W_hh + (2 * kp + 1) * 768 + jg;
            wrz4[i] = make_float4(wr0[0], wr1[0], wr0[256], wr1[256]);
            wn2_[i] = make_float2(wr0[512], wr1[512]);
        }
        for (int i = tid; i < Vz * 16; i += 256) {
            int v = i >> 4, e = i & 15;
            sm[OFF_EMB + v * 17 + e] = embed[i];
        }
        {
            float4* wih4 = (float4*)(sm + OFF_WIH);
            if (tid < 16 * 16) {
                int e = tid >> 4, j2 = tid & 15, jg = j0 + j2;
                wih4[tid] = make_float4(W_ih[e * 768 + jg],
                                        W_ih[e * 768 + 256 + jg],
                                        W_ih[e * 768 + 512 + jg], 0.f);
            }
        }
        {
            int4* xs4 = (int4*)(sm + OFF_X);
            const int4* xg = (const int4*)x;
            for (int i = tid; i < 2048; i += 256) {
                int bb = i >> 7, s4 = i & 127;
                xs4[i] = xg[(bA0 + bb) * 128 + s4];
            }
        }
        // zero both h buffers (h0 = 0)
        for (int i = tid; i < 2112; i += 256) {
            sm[OFF_HA + i] = 0.f;
            sm[OFF_HB + i] = 0.f;
        }

        // thread roles
        const int w   = tid >> 5, jl = tid & 31;
        const int bh  = jl >> 4, j2l = jl & 15;
        const int fb  = tid >> 4, fj = tid & 15;     // finalize (tid<128 only)
        const int jF  = j0 + fj;
        const int sr  = tid >> 5, sc = (tid & 31) * 4;   // stage mapping

        float3 bih = make_float3(b_ih[jF], b_ih[256 + jF], b_ih[512 + jF]);
        float3 bhh = make_float3(b_hh[jF], b_hh[256 + jF], b_hh[512 + jF]);
        float hprevA = 0.f, hprevB = 0.f;

        __syncthreads();
        // gi only meaningful (and only SAFE: xrow<16) for tid<128
        float3 giA = make_float3(0.f, 0.f, 0.f);
        float3 giB = make_float3(0.f, 0.f, 0.f);
        if (tid < 128) {
            giA = compute_gi2(sm, fb,     fj, 0, bih);
            giB = compute_gi2(sm, 8 + fb, fj, 0, bih);
        }

        float*  hsA  = sm + OFF_HA;
        float*  hsB  = sm + OFF_HB;
        float4* red4 = (float4*)(sm + OFF_RED);
        unsigned* barA = &g_bar[btA * 32];
        unsigned* barB = &g_bar[btB * 32];

        for (int t = 0; t < Sz; ++t) {
            // ================= A phase =================
            if (tid == 0) {                       // gate for LDG of B(t)
                unsigned tgt = 16u * (unsigned)t;
                while (ld_acquire_gpu(barB) < tgt) { }
            }
            chain_kloop(hsA, wrz4, wn2_, w, bh, j2l, red4);
            __syncthreads();                      // red ready; acquire propagated

            // prefetch B(t) (LDGs fly during finalize)
            const float* srcB = &g_hseq[t][bB0 + sr][0];
            float4 pB1 = *(const float4*)&srcB[sc];
            float4 pB2 = *(const float4*)&srcB[128 + sc];

            if (tid < 128) {                      // finalize chain A
                float sr_ = 0.f, sz_ = 0.f, sn_ = 0.f;
#pragma unroll
                for (int kc = 0; kc < 8; ++kc) {
                    float4 p = red4[(kc * 8 + fb) * 16 + fj];
                    sr_ += p.x; sz_ += p.y; sn_ += p.z;
                }
                float r = sigmf(giA.x + sr_ + bhh.x);
                float z = sigmf(giA.y + sz_ + bhh.y);
                float n = tanhf(giA.z + r * (sn_ + bhh.z));
                hprevA = (1.0f - z) * n + z * hprevA;
                g_hseq[t + 1][bA0 + fb][jF] = hprevA;
            }
            *(float4*)&hsB[sr * HSP + sc]       = pB1;
            *(float4*)&hsB[sr * HSP + 128 + sc] = pB2;
            __syncthreads();                      // finalize STGs + STS done
            if (tid == 0) red_release_gpu(barA);
            if (tid < 128 && t + 1 < Sz)
                giA = compute_gi2(sm, fb, fj, t + 1, bih);

            // ================= B phase =================
            if (tid == 0 && t + 1 < Sz) {         // gate for LDG of A(t+1)
                unsigned tgt = 16u * (unsigned)(t + 1);
                while (ld_acquire_gpu(barA) < tgt) { }
            }
            chain_kloop(hsB, wrz4, wn2_, w, bh, j2l, red4);
            __syncthreads();

            float4 pA1, pA2;
            if (t + 1 < Sz) {                     // prefetch A(t+1)
                const float* srcA = &g_hseq[t + 1][bA0 + sr][0];
                pA1 = *(const float4*)&srcA[sc];
                pA2 = *(const float4*)&srcA[128 + sc];
            }
            if (tid < 128) {                      // finalize chain B
                float sr_ = 0.f, sz_ = 0.f, sn_ = 0.f;
#pragma unroll
                for (int kc = 0; kc < 8; ++kc) {
                    float4 p = red4[(kc * 8 + fb) * 16 + fj];
                    sr_ += p.x; sz_ += p.y; sn_ += p.z;
                }
                float r = sigmf(giB.x + sr_ + bhh.x);
                float z = sigmf(giB.y + sz_ + bhh.y);
                float n = tanhf(giB.z + r * (sn_ + bhh.z));
                hprevB = (1.0f - z) * n + z * hprevB;
                g_hseq[t + 1][bB0 + fb][jF] = hprevB;
            }
            if (t + 1 < Sz) {
                *(float4*)&hsA[sr * HSP + sc]       = pA1;
                *(float4*)&hsA[sr * HSP + 128 + sc] = pA2;
            }
            __syncthreads();
            if (tid == 0) red_release_gpu(barB);
            if (tid < 128 && t + 1 < Sz)
                giB = compute_gi2(sm, 8 + fb, fj, t + 1, bih);
        }
        __syncthreads();
        // recurrence done: join the phase-2 tile queue
        p2_queue_loop(sm, tid, W_out, b_out, out, &s_tau);
    } else {
        // dedicated worker
        p2_queue_loop(sm, tid, W_out, b_out, out, &s_tau);
    }

    // reset counters for graph replay: last of all 148 CTAs resets.
    __threadfence();
    if (tid == 0) {
        unsigned d = atomicAdd(&g_done, 1u);
        if (d == (NP1 + NWORK) - 1u) {
            for (int i = 0; i < 16; ++i) g_bar[i * 32] = 0u;
            g_next = 0u;
            g_done = 0u;
            __threadfence();
        }
    }
}

extern "C" void kernel_launch(void* const* d_in, const int* in_sizes, int n_in,
                              void* d_out, int out_size)
{
    const int*   x     = (const int*)  d_in[0];
    const float* embed = (const float*)d_in[1];
    const float* W_ih  = (const float*)d_in[2];
    const float* b_ih  = (const float*)d_in[3];
    const float* W_hh  = (const float*)d_in[4];
    const float* b_hh  = (const float*)d_in[5];
    const float* W_out = (const float*)d_in[6];
    const float* b_out = (const float*)d_in[7];
    float* out = (float*)d_out;

    cudaFuncSetAttribute(gru_fused, cudaFuncAttributeMaxDynamicSharedMemorySize,
                         SMEM_BYTES);
    gru_fused<<<NP1 + NWORK, 256, SMEM_BYTES>>>(x, embed, W_ih, b_ih,
                                                W_hh, b_hh, W_out, b_out, out);
}